// round 13
// baseline (speedup 1.0000x reference)
#include <cuda_runtime.h>
#include <cstdint>
#include <math.h>

// ---------------------------------------------------------------------------
// PolicyGradientLoss: out = mean( nll(w,a) * (D - mean D) )
//   D[t] = sum_{k>=t} gamma^{k-t} r[k]       (reverse affine scan)
//   nll[t] = logsumexp(w[t,:]) - w[t, a[t]]
// Identity: mean(nll*(D-mD)) = (S_pd - S_d*S_n/T)/T
// ep_as is int32 on device.
//
// R13: warp-autonomous cp.async pipeline. Each warp ping-pongs 32-row
// micro-tiles through its private smem slice with __syncwarp only — zero
// block barriers in the mainloop (R12's per-tile block barriers convoyed
// all 8 warps on each tile copy, capping DRAM at 65%).
// ---------------------------------------------------------------------------

#define GAMMA 0.99f
#define BT 256                          // threads per block (8 warps)
#define FPT 8                           // rows per thread in scan
#define FCHUNK (BT * FPT)               // 2048 rows per block
#define MAXT (1 << 22)
#define MAXC (MAXT / FCHUNK)
#define AH 9                            // float2 per row (A = 18)
#define ROWB 72                         // bytes per row
#define WROWS 256                       // rows per warp
#define WTILE 32                        // rows per warp-tile
#define NT (WROWS / WTILE)              // 8 warp-tiles per warp
#define SLICE (WTILE * ROWB)            // 2304 B per buffer
#define NGR (SLICE / 16)                // 144 granules per warp-tile
#define WBUF_BYTES (8 * 2 * SLICE)      // 36864
#define DYNBYTES (WBUF_BYTES + FCHUNK * 4)  // 45056

static __device__ float  g_cg[MAXC];
static __device__ float  g_cs[MAXC];
static __device__ float  g_cin[MAXC];
static __device__ double g_acc[3];      // [0]=sum d, [1]=sum nll, [2]=sum nll*d
static __device__ unsigned int g_ctr;   // fused finish ticket
static __device__ unsigned int g_ctr2;  // agg finish ticket

__device__ __forceinline__ float gamma8() {
    float g2 = GAMMA * GAMMA; float g4 = g2 * g2; return g4 * g4;
}

__device__ __forceinline__ void cp16(unsigned int saddr, const void* gptr) {
    asm volatile("cp.async.cg.shared.global [%0], [%1], 16;"
                 :: "r"(saddr), "l"(gptr) : "memory");
}
__device__ __forceinline__ void cp_commit() {
    asm volatile("cp.async.commit_group;" ::: "memory");
}
template <int N>
__device__ __forceinline__ void cp_wait() {
    asm volatile("cp.async.wait_group %0;" :: "n"(N) : "memory");
}

// Issue one 32-row warp-tile copy (144 granules, lanes 0-15 do 5, 16-31 do 4)
__device__ __forceinline__ void issue_wtile(unsigned int dst, const char* src, int lane) {
    #pragma unroll
    for (int j = 0; j < 5; j++) {
        int i = lane + j * 32;
        if (i < NGR) cp16(dst + i * 16, src + i * 16);
    }
    cp_commit();
}

__device__ __forceinline__ void load8(const float* __restrict__ r, long long base,
                                      long long T, float rv[FPT]) {
    if (base + FPT <= T) {
        const float4* p = reinterpret_cast<const float4*>(r + base);
        float4 v0 = p[0], v1 = p[1];
        rv[0]=v0.x; rv[1]=v0.y; rv[2]=v0.z; rv[3]=v0.w;
        rv[4]=v1.x; rv[5]=v1.y; rv[6]=v1.z; rv[7]=v1.w;
    } else {
        #pragma unroll
        for (int j = 0; j < FPT; j++)
            rv[j] = (base + j < T) ? r[base + j] : 0.0f;
    }
}

// Warp inclusive suffix scan of affine (g,s): lane i -> aggregate [i..31].
__device__ __forceinline__ void warp_suffix_incl(float& g, float& s) {
    int lane = threadIdx.x & 31;
    #pragma unroll
    for (int off = 1; off < 32; off <<= 1) {
        float g2 = __shfl_down_sync(0xffffffffu, g, off);
        float s2 = __shfl_down_sync(0xffffffffu, s, off);
        if (lane + off < 32) { s = s + g * s2; g = g * g2; }
    }
}

// Carry entering this thread's segment given block-incoming carry cin.
__device__ __forceinline__ float thread_carry(float gseg, float sseg, float cin,
                                              float* shg, float* shs) {
    int lane = threadIdx.x & 31, wid = threadIdx.x >> 5;
    int nw = blockDim.x >> 5;
    float g = gseg, s = sseg;
    warp_suffix_incl(g, s);
    float ge = __shfl_down_sync(0xffffffffu, g, 1);
    float se = __shfl_down_sync(0xffffffffu, s, 1);
    if (lane == 31) { ge = 1.0f; se = 0.0f; }
    if (lane == 0) { shg[wid] = g; shs[wid] = s; }
    __syncthreads();
    float gw = 1.0f, sw = 0.0f;
    for (int wv = wid + 1; wv < nw; wv++) { sw = sw + gw * shs[wv]; gw = gw * shg[wv]; }
    return se + ge * (sw + gw * cin);
}

// Float warp reduce -> per-warp double partial -> warp0 double reduce -> atomics
__device__ __forceinline__ void block_reduce3f(float a, float b, float c) {
    #pragma unroll
    for (int o = 16; o > 0; o >>= 1) {
        a += __shfl_down_sync(0xffffffffu, a, o);
        b += __shfl_down_sync(0xffffffffu, b, o);
        c += __shfl_down_sync(0xffffffffu, c, o);
    }
    __shared__ double sa[8], sb[8], sc[8];
    int lane = threadIdx.x & 31, wid = threadIdx.x >> 5;
    if (lane == 0) { sa[wid] = (double)a; sb[wid] = (double)b; sc[wid] = (double)c; }
    __syncthreads();
    if (wid == 0) {
        int nw = blockDim.x >> 5;
        double da = (lane < nw) ? sa[lane] : 0.0;
        double db = (lane < nw) ? sb[lane] : 0.0;
        double dc = (lane < nw) ? sc[lane] : 0.0;
        #pragma unroll
        for (int o = 4; o > 0; o >>= 1) {
            da += __shfl_down_sync(0xffffffffu, da, o);
            db += __shfl_down_sync(0xffffffffu, db, o);
            dc += __shfl_down_sync(0xffffffffu, dc, o);
        }
        if (lane == 0) {
            atomicAdd(&g_acc[0], da);
            atomicAdd(&g_acc[1], db);
            atomicAdd(&g_acc[2], dc);
        }
    }
}

// ---------------------------------------------------------------------------
// Kernel 1: per-chunk aggregates; last-finished block runs the chunk scan,
// zeroes accumulators and tickets.
// ---------------------------------------------------------------------------
__global__ void __launch_bounds__(BT) k_agg(const float* __restrict__ r, long long T) {
    __shared__ float shg[BT / 32], shs[BT / 32];
    __shared__ int is_last;
    int tid = threadIdx.x;
    int nchunk = gridDim.x;
    long long base = (long long)blockIdx.x * FCHUNK + (long long)tid * FPT;
    float rv[FPT];
    load8(r, base, T, rv);
    int cnt = (int)max(0LL, min((long long)FPT, T - base));
    float carry = 0.0f;
    #pragma unroll
    for (int j = FPT - 1; j >= 0; --j) carry = carry * GAMMA + rv[j];
    float gseg = (cnt == FPT) ? gamma8() : __powf(GAMMA, (float)cnt);
    (void)thread_carry(gseg, carry, 0.0f, shg, shs);
    __syncthreads();
    if (tid == 0) {
        int nw = blockDim.x >> 5;
        float g = 1.0f, s = 0.0f;
        for (int wv = 0; wv < nw; wv++) { s = s + g * shs[wv]; g = g * shg[wv]; }
        g_cg[blockIdx.x] = g; g_cs[blockIdx.x] = s;
        __threadfence();
        is_last = (atomicAdd(&g_ctr2, 1u) == (unsigned)nchunk - 1u) ? 1 : 0;
    }
    __syncthreads();
    if (!is_last) return;

    // --- last block: suffix scan over chunk aggregates + housekeeping ---
    __threadfence();   // acquire other blocks' g_cg/g_cs
    if (tid == 0) { g_acc[0] = 0.0; g_acc[1] = 0.0; g_acc[2] = 0.0;
                    g_ctr = 0u; g_ctr2 = 0u; }
    __syncthreads();   // reuse shg/shs safely
    int kc = (nchunk + BT - 1) / BT;
    int lo = tid * kc;
    int hi = min(lo + kc, nchunk);
    float cg = 1.0f, cs = 0.0f;
    for (int c = lo; c < hi; c++) { cs = cs + cg * g_cs[c]; cg = cg * g_cg[c]; }
    float scarry = thread_carry(cg, cs, 0.0f, shg, shs);
    for (int c = hi - 1; c >= lo; --c) {
        g_cin[c] = scarry;
        scarry = g_cs[c] + g_cg[c] * scarry;
    }
}

// ---------------------------------------------------------------------------
// Kernel 2 (fused): scan replay + warp-autonomous cp.async loss pipeline.
// Last-block ticket computes the final scalar. A == 18 specialization.
// ---------------------------------------------------------------------------
__global__ void __launch_bounds__(BT) k_fused18(const float* __restrict__ w,
                                                const float* __restrict__ r,
                                                const int* __restrict__ as,
                                                long long T, float* out) {
    extern __shared__ __align__(16) char dyns[];
    char*  wbuf = dyns;                                            // 8 warps * 2 * SLICE
    float* sd   = reinterpret_cast<float*>(dyns + WBUF_BYTES);     // FCHUNK floats
    __shared__ float shg[BT / 32], shs[BT / 32];
    int tid = threadIdx.x;
    int lane = tid & 31, wid = tid >> 5;
    long long cbase = (long long)blockIdx.x * FCHUNK;
    bool full = (cbase + FCHUNK <= T);
    long long wrow = cbase + (long long)wid * WROWS;               // this warp's rows
    const char* wsrc = reinterpret_cast<const char*>(w) + wrow * ROWB;

    unsigned int sbA = (unsigned int)__cvta_generic_to_shared(wbuf + (wid * 2 + 0) * SLICE);
    unsigned int sbB = (unsigned int)__cvta_generic_to_shared(wbuf + (wid * 2 + 1) * SLICE);

    // prologue: each warp issues its first two micro-tiles (overlap with scan)
    if (full) {
        issue_wtile(sbA, wsrc, lane);
        issue_wtile(sbB, wsrc + SLICE, lane);
    }

    // --- scan replay for this chunk ---
    long long base = cbase + (long long)tid * FPT;
    float rv[FPT];
    load8(r, base, T, rv);
    int cnt = (int)max(0LL, min((long long)FPT, T - base));
    float carry = 0.0f;
    #pragma unroll
    for (int j = FPT - 1; j >= 0; --j) carry = carry * GAMMA + rv[j];
    float gseg = (cnt == FPT) ? gamma8() : __powf(GAMMA, (float)cnt);
    float tc = thread_carry(gseg, carry, g_cin[blockIdx.x], shg, shs);

    float dsum = 0.0f;
    {
        float c2 = tc;
        if (cnt == FPT) {
            float dloc[FPT];
            #pragma unroll
            for (int j = FPT - 1; j >= 0; --j) { c2 = c2 * GAMMA + rv[j]; dloc[j] = c2; }
            #pragma unroll
            for (int j = 0; j < FPT; j++) { sd[tid * FPT + j] = dloc[j]; dsum += dloc[j]; }
        } else {
            for (int j = FPT - 1; j >= 0; --j) {
                if (j < cnt) { c2 = c2 * GAMMA + rv[j]; sd[tid * FPT + j] = c2; dsum += c2; }
                else sd[tid * FPT + j] = 0.0f;
            }
        }
    }
    __syncthreads();   // sd visible to all warps (last block barrier before reduce)

    float pn = 0.0f, pp = 0.0f;

    if (full) {
        const float* sdw = sd + wid * WROWS;
        #pragma unroll
        for (int k = 0; k < NT; k++) {
            if (k < NT - 1) cp_wait<1>(); else cp_wait<0>();
            __syncwarp();              // tile k's slice visible warp-wide

            const float2* st = reinterpret_cast<const float2*>(
                wbuf + (wid * 2 + (k & 1)) * SLICE);
            long long t = wrow + (long long)k * WTILE + lane;
            int ai = as[t];
            const float2* myrow = st + lane * AH;
            float s0 = 0.0f, s1 = 0.0f;
            #pragma unroll
            for (int i = 0; i < AH; i++) {
                float2 v = myrow[i];
                s0 += __expf(v.x);
                s1 += __expf(v.y);
            }
            float2 va = myrow[ai >> 1];
            float wa = (ai & 1) ? va.y : va.x;
            float nll = __logf(s0 + s1) - wa;
            float d = sdw[k * WTILE + lane];
            pn += nll;
            pp += nll * d;

            __syncwarp();              // reads done before this buffer is reissued
            if (k + 2 < NT) {
                unsigned int dst = (k & 1) ? sbB : sbA;   // buffer (k+2)&1 == k&1
                issue_wtile(dst, wsrc + (long long)(k + 2) * SLICE, lane);
            }
        }
    } else {
        // partial last chunk: direct loads (at most one block)
        for (int k = 0; k < NT; k++) {
            long long t = wrow + (long long)k * WTILE + lane;
            if (t < T) {
                const float* row = w + (size_t)t * (AH * 2);
                const float2* p2 = reinterpret_cast<const float2*>(row);
                float s = 0.0f;
                #pragma unroll
                for (int i = 0; i < AH; i++) {
                    float2 v = __ldg(p2 + i);
                    s += __expf(v.x) + __expf(v.y);
                }
                int ai = as[t];
                float nll = __logf(s) - __ldg(row + ai);
                pn += nll;
                pp += nll * sd[wid * WROWS + k * WTILE + lane];
            }
        }
    }

    block_reduce3f(dsum, pn, pp);

    if (tid == 0) {
        __threadfence();
        if (atomicAdd(&g_ctr, 1u) == gridDim.x - 1) {
            __threadfence();
            double Td = (double)T;
            double ds = g_acc[0], ns = g_acc[1], ps = g_acc[2];
            out[0] = (float)((ps - ds * ns / Td) / Td);
            g_ctr = 0u;
        }
    }
}

// Generic-A fallback (direct loads, float accumulators)
__global__ void __launch_bounds__(BT) k_fused_gen(const float* __restrict__ w,
                                                  const float* __restrict__ r,
                                                  const int* __restrict__ as,
                                                  long long T, int A, float* out) {
    extern __shared__ __align__(16) char dyns[];
    float* sd = reinterpret_cast<float*>(dyns + WBUF_BYTES);
    __shared__ float shg[BT / 32], shs[BT / 32];
    int tid = threadIdx.x;
    long long cbase = (long long)blockIdx.x * FCHUNK;
    long long base = cbase + (long long)tid * FPT;

    float rv[FPT];
    load8(r, base, T, rv);
    int cnt = (int)max(0LL, min((long long)FPT, T - base));
    float carry = 0.0f;
    #pragma unroll
    for (int j = FPT - 1; j >= 0; --j) carry = carry * GAMMA + rv[j];
    float gseg = (cnt == FPT) ? gamma8() : __powf(GAMMA, (float)cnt);
    float tc = thread_carry(gseg, carry, g_cin[blockIdx.x], shg, shs);

    float dsum = 0.0f;
    {
        float c2 = tc;
        for (int j = FPT - 1; j >= 0; --j) {
            if (j < cnt) { c2 = c2 * GAMMA + rv[j]; sd[tid * FPT + j] = c2; dsum += c2; }
            else sd[tid * FPT + j] = 0.0f;
        }
    }
    __syncthreads();

    float pn = 0.0f, pp = 0.0f;
    for (int j = 0; j < FPT; j++) {
        long long t = cbase + (long long)j * BT + tid;
        if (t < T) {
            const float* row = w + (size_t)t * A;
            float m = __ldg(row);
            for (int i = 1; i < A; i++) m = fmaxf(m, __ldg(row + i));
            float s = 0.0f;
            for (int i = 0; i < A; i++) s += __expf(__ldg(row + i) - m);
            int ai = as[t];
            float nll = m + __logf(s) - __ldg(row + ai);
            pn += nll;
            pp += nll * sd[j * BT + tid];
        }
    }
    __syncthreads();
    block_reduce3f(dsum, pn, pp);

    if (tid == 0) {
        __threadfence();
        if (atomicAdd(&g_ctr, 1u) == gridDim.x - 1) {
            __threadfence();
            double Td = (double)T;
            double ds = g_acc[0], ns = g_acc[1], ps = g_acc[2];
            out[0] = (float)((ps - ds * ns / Td) / Td);
            g_ctr = 0u;
        }
    }
}

extern "C" void kernel_launch(void* const* d_in, const int* in_sizes, int n_in,
                              void* d_out, int out_size) {
    const float* w  = (const float*)d_in[0];   // [T, A]
    const float* r  = (const float*)d_in[1];   // [T]
    const int*   as = (const int*)d_in[2];     // [T] int32
    long long T = (long long)in_sizes[1];
    int A = (int)((long long)in_sizes[0] / T);
    long long NCll = (T + FCHUNK - 1) / FCHUNK;
    if (NCll > MAXC) NCll = MAXC;
    int NC = (int)NCll;

    static int attr_done = 0;
    if (!attr_done) {
        cudaFuncSetAttribute(k_fused18, cudaFuncAttributeMaxDynamicSharedMemorySize, DYNBYTES);
        cudaFuncSetAttribute(k_fused_gen, cudaFuncAttributeMaxDynamicSharedMemorySize, DYNBYTES);
        attr_done = 1;
    }

    k_agg<<<NC, BT>>>(r, T);
    if (A == 18) k_fused18<<<NC, BT, DYNBYTES>>>(w, r, as, T, (float*)d_out);
    else         k_fused_gen<<<NC, BT, DYNBYTES>>>(w, r, as, T, A, (float*)d_out);
}